// round 1
// baseline (speedup 1.0000x reference)
#include <cuda_runtime.h>

#define NADDR 150000
#define NTX   200000
#define INDIM 64
#define HID   32
#define HEADS 4
#define EAT   1000000
#define ETA   1000000
#define EAA   500000

// ---------------- scratch (static device globals; no dynamic alloc) ----------------
__device__ float g_hA[NADDR*HID];      // projected addr features (current layer)
__device__ float g_hT[NTX*HID];        // projected tx features
__device__ float g_accT[NTX*HID];      // relation accum / o_tx (becomes next-layer tx input)
__device__ float g_accA1[NADDR*HID];   // o_a1 (ta relation)
__device__ float g_accA2[NADDR*HID];   // o_a2 (aa relation)
__device__ float g_bufA[NADDR*HID];    // semantic-combined addr output (next-layer addr input)
__device__ float g_sT[NTX*HEADS];      // softmax denominators
__device__ float g_sA1[NADDR*HEADS];
__device__ float g_sA2[NADDR*HEADS];
__device__ float g_as0[NADDR*HEADS];   // alpha_src for relation 0 (addr as src)
__device__ float g_ad1[NADDR*HEADS];   // alpha_dst for relation 1 (addr as dst)
__device__ float g_as2[NADDR*HEADS];   // alpha_src for relation 2
__device__ float g_ad2[NADDR*HEADS];   // alpha_dst for relation 2
__device__ float g_tad0[NTX*HEADS];    // alpha_dst rel 0 (tx as dst)
__device__ float g_tas1[NTX*HEADS];    // alpha_src rel 1 (tx as src)
__device__ float g_tacc[2*HID];        // semantic tanh-mean accumulators
__device__ float g_attn[2];            // semantic attention weights

__device__ __forceinline__ void red_v4(float* a, float x, float y, float z, float w) {
    asm volatile("red.global.add.v4.f32 [%0], {%1,%2,%3,%4};"
                 :: "l"(a), "f"(x), "f"(y), "f"(z), "f"(w) : "memory");
}

// ---------------- zero scratch (replaces memsets; graph-capturable kernel) ----------
__global__ void zero_kernel() {
    int i = blockIdx.x * blockDim.x + threadIdx.x;
    int stride = gridDim.x * blockDim.x;
    for (int k = i; k < NTX*HID; k += stride) g_accT[k] = 0.f;
    for (int k = i; k < NADDR*HID; k += stride) { g_accA1[k] = 0.f; g_accA2[k] = 0.f; }
    for (int k = i; k < NTX*HEADS; k += stride) g_sT[k] = 0.f;
    for (int k = i; k < NADDR*HEADS; k += stride) { g_sA1[k] = 0.f; g_sA2[k] = 0.f; }
    if (i < 2*HID) g_tacc[i] = 0.f;
}

// ---------------- linear projection: y[n,32] = x[n,:IN] @ W[IN,32] + b ----------------
// in_sel: 0 = external x, 1 = g_bufA, 2 = g_accT.  out_sel: 0 = g_hA, 1 = g_hT.
__global__ void lin_kernel(int in_sel, const float* __restrict__ x_ext,
                           const float* __restrict__ W, const float* __restrict__ b,
                           int out_sel, int N, int IN) {
    __shared__ float Ws[INDIM*HID];
    const float* x = (in_sel == 0) ? x_ext : (in_sel == 1 ? (const float*)g_bufA
                                                          : (const float*)g_accT);
    float* y = out_sel ? g_hT : g_hA;
    int tid = threadIdx.x;
    for (int i = tid; i < IN*HID; i += 256) Ws[i] = W[i];
    __syncthreads();
    int n = blockIdx.x * 8 + (tid >> 5);
    int j = tid & 31;
    if (n >= N) return;
    const float* xr = x + (long)n * IN;
    float acc = b[j];
    #pragma unroll 8
    for (int k = 0; k < IN; k++) acc = fmaf(xr[k], Ws[k*HID + j], acc);
    y[(long)n*HID + j] = acc;
}

__device__ __forceinline__ float dot8(float4 a, float4 b, const float* __restrict__ v) {
    return a.x*v[0] + a.y*v[1] + a.z*v[2] + a.w*v[3]
         + b.x*v[4] + b.y*v[5] + b.z*v[6] + b.w*v[7];
}

// ---------------- per-node per-head attention dot products -------------------------
__global__ void alpha_addr_kernel(const float* __restrict__ v_as0, const float* __restrict__ v_ad1,
                                  const float* __restrict__ v_as2, const float* __restrict__ v_ad2) {
    int i = blockIdx.x * blockDim.x + threadIdx.x;
    if (i >= NADDR*HEADS) return;
    int n = i >> 2, hh = i & 3;
    const float* hr = g_hA + (long)n*HID + hh*8;
    float4 a = *(const float4*)hr;
    float4 b = *(const float4*)(hr + 4);
    g_as0[i] = dot8(a, b, v_as0 + hh*8);
    g_ad1[i] = dot8(a, b, v_ad1 + hh*8);
    g_as2[i] = dot8(a, b, v_as2 + hh*8);
    g_ad2[i] = dot8(a, b, v_ad2 + hh*8);
}

__global__ void alpha_tx_kernel(const float* __restrict__ v_ad0, const float* __restrict__ v_as1) {
    int i = blockIdx.x * blockDim.x + threadIdx.x;
    if (i >= NTX*HEADS) return;
    int n = i >> 2, hh = i & 3;
    const float* hr = g_hT + (long)n*HID + hh*8;
    float4 a = *(const float4*)hr;
    float4 b = *(const float4*)(hr + 4);
    g_tad0[i] = dot8(a, b, v_ad0 + hh*8);
    g_tas1[i] = dot8(a, b, v_as1 + hh*8);
}

// ---------------- fused edge pass: unnormalized softmax scatter --------------------
// 4 threads per edge (one per head). out[d] += e*h_src ; s[d] += e.
__global__ void edge_kernel(int rel, const int* __restrict__ src,
                            const int* __restrict__ dst, int E) {
    const float *asv, *adv, *hs;
    float *sp, *ap;
    if (rel == 0)      { asv = g_as0;  adv = g_tad0; hs = g_hA; sp = g_sT;  ap = g_accT;  }
    else if (rel == 1) { asv = g_tas1; adv = g_ad1;  hs = g_hT; sp = g_sA1; ap = g_accA1; }
    else               { asv = g_as2;  adv = g_ad2;  hs = g_hA; sp = g_sA2; ap = g_accA2; }

    int i = blockIdx.x * blockDim.x + threadIdx.x;
    int e = i >> 2, hh = i & 3;
    bool valid = e < E;
    int ec = valid ? e : 0;
    int s = __ldg(src + ec), d = __ldg(dst + ec);
    float l = __ldg(asv + s*4 + hh) + __ldg(adv + d*4 + hh);
    l = (l >= 0.f) ? l : 0.2f * l;                 // leaky_relu, slope 0.2
    float ev = valid ? __expf(l) : 0.f;

    // coalesce the 4 head denominators into one red.v4 (lane groups of 4)
    float e0 = __shfl_sync(0xffffffffu, ev, 0, 4);
    float e1 = __shfl_sync(0xffffffffu, ev, 1, 4);
    float e2 = __shfl_sync(0xffffffffu, ev, 2, 4);
    float e3 = __shfl_sync(0xffffffffu, ev, 3, 4);
    if (hh == 0) red_v4(sp + (long)d*4, e0, e1, e2, e3);

    const float* hr = hs + (long)s*HID + hh*8;
    float4 a = *(const float4*)hr;
    float4 b = *(const float4*)(hr + 4);
    float* op = ap + (long)d*HID + hh*8;
    red_v4(op,     ev*a.x, ev*a.y, ev*a.z, ev*a.w);
    red_v4(op + 4, ev*b.x, ev*b.y, ev*b.z, ev*b.w);
}

// ---------------- normalize + relu (in place) --------------------------------------
__global__ void norm_kernel(int rel) {
    float* acc; const float* s; int N;
    if (rel == 0)      { acc = g_accT;  s = g_sT;  N = NTX;   }
    else if (rel == 1) { acc = g_accA1; s = g_sA1; N = NADDR; }
    else               { acc = g_accA2; s = g_sA2; N = NADDR; }
    int i = blockIdx.x * blockDim.x + threadIdx.x;
    if (i >= N*HID) return;
    int n = i >> 5, f = i & 31;
    float v = acc[i] / (s[n*4 + (f >> 3)] + 1e-16f);
    acc[i] = v > 0.f ? v : 0.f;
}

// ---------------- semantic attention: mean over nodes of tanh(o @ kW + kb) ---------
__global__ void sem_mean_kernel(int r, const float* __restrict__ kW, const float* __restrict__ kb) {
    __shared__ float Ws[HID*HID];
    __shared__ float redbuf[256];
    const float* o = r ? (const float*)g_accA2 : (const float*)g_accA1;
    int tid = threadIdx.x;
    for (int i = tid; i < HID*HID; i += 256) Ws[i] = kW[i];
    __syncthreads();
    int j = tid & 31, slot = tid >> 5;
    float bj = kb[j];
    float accv = 0.f;
    int n0 = blockIdx.x * 256 + slot;
    for (int it = 0; it < 32; it++) {
        int n = n0 + it*8;
        if (n < NADDR) {
            const float* orow = o + (long)n*HID;
            float dot = bj;
            #pragma unroll
            for (int k = 0; k < HID; k++) dot = fmaf(orow[k], Ws[k*HID + j], dot);
            accv += tanhf(dot);
        }
    }
    redbuf[tid] = accv;
    __syncthreads();
    if (slot == 0) {
        float sum = 0.f;
        #pragma unroll
        for (int ss = 0; ss < 8; ss++) sum += redbuf[ss*32 + j];
        atomicAdd(&g_tacc[r*HID + j], sum);
    }
}

__global__ void attn_kernel(const float* __restrict__ q) {
    const float invN = 1.f / (float)NADDR;
    float s0 = 0.f, s1 = 0.f;
    for (int j = 0; j < HID; j++) {
        s0 += g_tacc[j] * invN * q[j];
        s1 += g_tacc[HID + j] * invN * q[j];
    }
    float m = fmaxf(s0, s1);
    float e0 = expf(s0 - m), e1 = expf(s1 - m);
    g_attn[0] = e0 / (e0 + e1);
    g_attn[1] = e1 / (e0 + e1);
}

__global__ void combine_kernel() {
    int i = blockIdx.x * blockDim.x + threadIdx.x;
    if (i >= NADDR*HID) return;
    float v = g_attn[0]*g_accA1[i] + g_attn[1]*g_accA2[i];
    g_bufA[i] = v > 0.f ? v : 0.f;   // wrapper relu (identity here, kept for safety)
}

// ---------------- final linear: out[n,2] = a[n,:] @ linW + linb --------------------
__global__ void final_kernel(const float* __restrict__ W, const float* __restrict__ b,
                             float* __restrict__ out) {
    int n = blockIdx.x * blockDim.x + threadIdx.x;
    if (n >= NADDR) return;
    float a0 = b[0], a1 = b[1];
    const float* ar = g_bufA + (long)n*HID;
    #pragma unroll
    for (int k = 0; k < HID; k++) {
        float v = ar[k];
        a0 = fmaf(v, W[k*2],     a0);
        a1 = fmaf(v, W[k*2 + 1], a1);
    }
    out[n*2] = a0;
    out[n*2 + 1] = a1;
}

// ---------------- host orchestration ----------------------------------------------
extern "C" void kernel_launch(void* const* d_in, const int* in_sizes, int n_in,
                              void* d_out, int out_size) {
    const float* x_addr  = (const float*)d_in[0];
    const float* x_tx    = (const float*)d_in[1];
    const int*   eat_s   = (const int*)d_in[2];
    const int*   eat_d   = (const int*)d_in[3];
    const int*   eta_s   = (const int*)d_in[4];
    const int*   eta_d   = (const int*)d_in[5];
    const int*   eaa_s   = (const int*)d_in[6];
    const int*   eaa_d   = (const int*)d_in[7];
    const float* pW1     = (const float*)d_in[8];
    const float* pb1     = (const float*)d_in[9];
    const float* pW23    = (const float*)d_in[10];
    const float* pb23    = (const float*)d_in[11];
    const float* att_src = (const float*)d_in[12];
    const float* att_dst = (const float*)d_in[13];
    const float* kW      = (const float*)d_in[14];
    const float* kb      = (const float*)d_in[15];
    const float* q       = (const float*)d_in[16];
    const float* linW    = (const float*)d_in[17];
    const float* linb    = (const float*)d_in[18];

    for (int l = 0; l < 3; l++) {
        const float *Wa, *ba, *Wt, *bt;
        int IN, in_a, in_t;
        if (l == 0) {
            Wa = pW1;               ba = pb1;
            Wt = pW1 + INDIM*HID;   bt = pb1 + HID;
            IN = INDIM; in_a = 0; in_t = 0;
        } else {
            Wa = pW23 + ((l-1)*2 + 0)*HID*HID;  ba = pb23 + ((l-1)*2 + 0)*HID;
            Wt = pW23 + ((l-1)*2 + 1)*HID*HID;  bt = pb23 + ((l-1)*2 + 1)*HID;
            IN = HID; in_a = 1; in_t = 2;
        }
        // projections read previous-layer buffers BEFORE they are zeroed
        lin_kernel<<<(NADDR + 7)/8, 256>>>(in_a, x_addr, Wa, ba, 0, NADDR, IN);
        lin_kernel<<<(NTX   + 7)/8, 256>>>(in_t, x_tx,   Wt, bt, 1, NTX,   IN);
        zero_kernel<<<1024, 256>>>();

        const float* As = att_src + (l*3) * HEADS * 8;
        const float* Ad = att_dst + (l*3) * HEADS * 8;
        alpha_addr_kernel<<<(NADDR*HEADS + 255)/256, 256>>>(As + 0*32, Ad + 1*32,
                                                            As + 2*32, Ad + 2*32);
        alpha_tx_kernel<<<(NTX*HEADS + 255)/256, 256>>>(Ad + 0*32, As + 1*32);

        edge_kernel<<<(EAT*4 + 255)/256, 256>>>(0, eat_s, eat_d, EAT);
        edge_kernel<<<(ETA*4 + 255)/256, 256>>>(1, eta_s, eta_d, ETA);
        edge_kernel<<<(EAA*4 + 255)/256, 256>>>(2, eaa_s, eaa_d, EAA);

        norm_kernel<<<(NTX*HID   + 255)/256, 256>>>(0);
        norm_kernel<<<(NADDR*HID + 255)/256, 256>>>(1);
        norm_kernel<<<(NADDR*HID + 255)/256, 256>>>(2);

        sem_mean_kernel<<<(NADDR + 255)/256, 256>>>(0, kW + l*HID*HID, kb + l*HID);
        sem_mean_kernel<<<(NADDR + 255)/256, 256>>>(1, kW + l*HID*HID, kb + l*HID);
        attn_kernel<<<1, 1>>>(q + l*HID);
        combine_kernel<<<(NADDR*HID + 255)/256, 256>>>();
        // tx semantic attention over a single relation is identity: next t = g_accT
    }
    final_kernel<<<(NADDR + 255)/256, 256>>>(linW, linb, (float*)d_out);
}

// round 5
// speedup vs baseline: 1.5879x; 1.5879x over previous
#include <cuda_runtime.h>

#define NADDR 150000
#define NTX   200000
#define INDIM 64
#define HID   32
#define HEADS 4
#define EAT   1000000
#define ETA   1000000
#define EAA   500000

// ---------------- scratch (static device globals; no dynamic alloc) ----------------
__device__ float g_hA[NADDR*HID];      // projected addr features (current layer)
__device__ float g_hT[NTX*HID];        // projected tx features
__device__ float g_accT[NTX*HID];      // o_tx (becomes next-layer tx input)
__device__ float g_accA1[NADDR*HID];   // o_a1 (ta relation)
__device__ float g_accA2[NADDR*HID];   // o_a2 (aa relation)
__device__ float g_bufA[NADDR*HID];    // semantic-combined addr output
__device__ float g_as0[NADDR*HEADS];   // alpha_src rel0 (addr as src)
__device__ float g_ad1[NADDR*HEADS];   // alpha_dst rel1 (addr as dst)
__device__ float g_as2[NADDR*HEADS];   // alpha_src rel2
__device__ float g_ad2[NADDR*HEADS];   // alpha_dst rel2
__device__ float g_tad0[NTX*HEADS];    // alpha_dst rel0 (tx as dst)
__device__ float g_tas1[NTX*HEADS];    // alpha_src rel1 (tx as src)
__device__ float g_tacc[2*HID];        // semantic tanh-mean accumulators
__device__ float g_attn[2];            // semantic attention weights

// CSR scratch (built once per launch; edge lists are layer-invariant)
__device__ int g_offsT[NTX + 1];
__device__ int g_offsA1[NADDR + 1];
__device__ int g_offsA2[NADDR + 1];
__device__ int g_csr0[EAT];            // source ids grouped by dst
__device__ int g_csr1[ETA];
__device__ int g_csr2[EAA];
__device__ int g_cnt[NTX];             // temps (max Ndst)
__device__ int g_cur[NTX];
__device__ int g_bsums[256];

__device__ __forceinline__ int* offs_ptr(int rel) {
    return rel == 0 ? g_offsT : (rel == 1 ? g_offsA1 : g_offsA2);
}
__device__ __forceinline__ int* csr_ptr(int rel) {
    return rel == 0 ? g_csr0 : (rel == 1 ? g_csr1 : g_csr2);
}

// ---------------- CSR build ---------------------------------------------------------
__global__ void zero_cnt_kernel(int Nd) {
    int i = blockIdx.x * blockDim.x + threadIdx.x;
    if (i < Nd) g_cnt[i] = 0;
}
__global__ void count_kernel(const int* __restrict__ dst, int E) {
    int e = blockIdx.x * blockDim.x + threadIdx.x;
    if (e < E) atomicAdd(&g_cnt[dst[e]], 1);
}
// hierarchical exclusive scan of g_cnt[0..N) -> offs; 1024 items per block
__global__ void scan1_kernel(int rel, int N) {
    __shared__ int ts[256];
    int* offs = offs_ptr(rel);
    int tid = threadIdx.x;
    int base = blockIdx.x * 1024;
    int v[4]; int sum = 0;
    #pragma unroll
    for (int j = 0; j < 4; j++) {
        int idx = base + tid * 4 + j;
        v[j] = (idx < N) ? g_cnt[idx] : 0;
        sum += v[j];
    }
    ts[tid] = sum;
    __syncthreads();
    for (int off = 1; off < 256; off <<= 1) {
        int t = (tid >= off) ? ts[tid - off] : 0;
        __syncthreads();
        ts[tid] += t;
        __syncthreads();
    }
    int run = ts[tid] - sum;    // exclusive prefix within block
    #pragma unroll
    for (int j = 0; j < 4; j++) {
        int idx = base + tid * 4 + j;
        if (idx < N) offs[idx] = run;
        run += v[j];
    }
    if (tid == 255) g_bsums[blockIdx.x] = ts[255];
}
__global__ void scan2_kernel(int B) {
    __shared__ int ts[256];
    int tid = threadIdx.x;
    int v = (tid < B) ? g_bsums[tid] : 0;
    ts[tid] = v;
    __syncthreads();
    for (int off = 1; off < 256; off <<= 1) {
        int t = (tid >= off) ? ts[tid - off] : 0;
        __syncthreads();
        ts[tid] += t;
        __syncthreads();
    }
    if (tid < B) g_bsums[tid] = ts[tid] - v;   // exclusive
}
__global__ void scan3_kernel(int rel, int N, int E) {
    int* offs = offs_ptr(rel);
    int i = blockIdx.x * blockDim.x + threadIdx.x;
    if (i < N) {
        int o = offs[i] + g_bsums[i >> 10];
        offs[i] = o;
        g_cur[i] = o;
    }
    if (i == 0) offs[N] = E;
}
__global__ void scatter_kernel(int rel, const int* __restrict__ src,
                               const int* __restrict__ dst, int E) {
    int* csr = csr_ptr(rel);
    int e = blockIdx.x * blockDim.x + threadIdx.x;
    if (e >= E) return;
    int pos = atomicAdd(&g_cur[dst[e]], 1);
    csr[pos] = src[e];
}

// ---------------- linear projection: y[n,32] = x[n,:IN] @ W[IN,32] + b --------------
// in_sel: 0 = external x, 1 = g_bufA, 2 = g_accT.  out_sel: 0 = g_hA, 1 = g_hT.
__global__ void lin_kernel(int in_sel, const float* __restrict__ x_ext,
                           const float* __restrict__ W, const float* __restrict__ b,
                           int out_sel, int N, int IN) {
    __shared__ float Ws[INDIM*HID];
    const float* x = (in_sel == 0) ? x_ext : (in_sel == 1 ? (const float*)g_bufA
                                                          : (const float*)g_accT);
    float* y = out_sel ? g_hT : g_hA;
    int tid = threadIdx.x;
    for (int i = tid; i < IN*HID; i += 256) Ws[i] = W[i];
    __syncthreads();
    int n = blockIdx.x * 8 + (tid >> 5);
    int j = tid & 31;
    if (n >= N) return;
    const float* xr = x + (long)n * IN;
    float acc = b[j];
    #pragma unroll 8
    for (int k = 0; k < IN; k++) acc = fmaf(xr[k], Ws[k*HID + j], acc);
    y[(long)n*HID + j] = acc;
}

__device__ __forceinline__ float dot8(float4 a, float4 b, const float* __restrict__ v) {
    return a.x*v[0] + a.y*v[1] + a.z*v[2] + a.w*v[3]
         + b.x*v[4] + b.y*v[5] + b.z*v[6] + b.w*v[7];
}

// ---------------- per-node per-head attention dot products --------------------------
__global__ void alpha_addr_kernel(const float* __restrict__ v_as0, const float* __restrict__ v_ad1,
                                  const float* __restrict__ v_as2, const float* __restrict__ v_ad2) {
    int i = blockIdx.x * blockDim.x + threadIdx.x;
    if (i >= NADDR*HEADS) return;
    int n = i >> 2, hh = i & 3;
    const float* hr = g_hA + (long)n*HID + hh*8;
    float4 a = *(const float4*)hr;
    float4 b = *(const float4*)(hr + 4);
    g_as0[i] = dot8(a, b, v_as0 + hh*8);
    g_ad1[i] = dot8(a, b, v_ad1 + hh*8);
    g_as2[i] = dot8(a, b, v_as2 + hh*8);
    g_ad2[i] = dot8(a, b, v_ad2 + hh*8);
}

__global__ void alpha_tx_kernel(const float* __restrict__ v_ad0, const float* __restrict__ v_as1) {
    int i = blockIdx.x * blockDim.x + threadIdx.x;
    if (i >= NTX*HEADS) return;
    int n = i >> 2, hh = i & 3;
    const float* hr = g_hT + (long)n*HID + hh*8;
    float4 a = *(const float4*)hr;
    float4 b = *(const float4*)(hr + 4);
    g_tad0[i] = dot8(a, b, v_ad0 + hh*8);
    g_tas1[i] = dot8(a, b, v_as1 + hh*8);
}

// ---------------- gather aggregation: softmax-weighted sum + normalize + relu -------
// one warp per destination node; 32 lanes = 32 features (lane>>3 = head)
__global__ void agg_kernel(int rel) {
    const int *offs, *csr;
    const float *asv, *adv, *hs;
    float* out;
    int N;
    if (rel == 0)      { offs = g_offsT;  csr = g_csr0; asv = g_as0;  adv = g_tad0;
                         hs = g_hA; out = g_accT;  N = NTX;   }
    else if (rel == 1) { offs = g_offsA1; csr = g_csr1; asv = g_tas1; adv = g_ad1;
                         hs = g_hT; out = g_accA1; N = NADDR; }
    else               { offs = g_offsA2; csr = g_csr2; asv = g_as2;  adv = g_ad2;
                         hs = g_hA; out = g_accA2; N = NADDR; }

    int n = blockIdx.x * 8 + (threadIdx.x >> 5);
    if (n >= N) return;
    int lane = threadIdx.x & 31;
    int h = lane >> 3;
    float ad = __ldg(adv + n*4 + h);
    int beg = offs[n], end = offs[n+1];
    float acc = 0.f, den = 0.f;
    for (int k = beg; k < end; k++) {
        int s = __ldg(csr + k);
        float l = __ldg(asv + s*4 + h) + ad;
        l = (l >= 0.f) ? l : 0.2f * l;          // leaky_relu slope 0.2
        float ev = __expf(l);
        den += ev;
        acc = fmaf(ev, __ldg(hs + (long)s*HID + lane), acc);
    }
    float v = acc / (den + 1e-16f);
    out[(long)n*HID + lane] = v > 0.f ? v : 0.f;
}

// ---------------- semantic attention ------------------------------------------------
__global__ void zero_tacc_kernel() {
    int i = threadIdx.x;
    if (i < 2*HID) g_tacc[i] = 0.f;
}

__global__ void sem_mean_kernel(int r, const float* __restrict__ kW, const float* __restrict__ kb) {
    __shared__ float Ws[HID*HID];
    __shared__ float redbuf[256];
    const float* o = r ? (const float*)g_accA2 : (const float*)g_accA1;
    int tid = threadIdx.x;
    for (int i = tid; i < HID*HID; i += 256) Ws[i] = kW[i];
    __syncthreads();
    int j = tid & 31, slot = tid >> 5;
    float bj = kb[j];
    float accv = 0.f;
    int n0 = blockIdx.x * 256 + slot;
    for (int it = 0; it < 32; it++) {
        int n = n0 + it*8;
        if (n < NADDR) {
            const float* orow = o + (long)n*HID;
            float dot = bj;
            #pragma unroll
            for (int k = 0; k < HID; k++) dot = fmaf(orow[k], Ws[k*HID + j], dot);
            accv += tanhf(dot);
        }
    }
    redbuf[tid] = accv;
    __syncthreads();
    if (slot == 0) {
        float sum = 0.f;
        #pragma unroll
        for (int ss = 0; ss < 8; ss++) sum += redbuf[ss*32 + j];
        atomicAdd(&g_tacc[r*HID + j], sum);
    }
}

__global__ void attn_kernel(const float* __restrict__ q) {
    const float invN = 1.f / (float)NADDR;
    float s0 = 0.f, s1 = 0.f;
    for (int j = 0; j < HID; j++) {
        s0 += g_tacc[j] * invN * q[j];
        s1 += g_tacc[HID + j] * invN * q[j];
    }
    float m = fmaxf(s0, s1);
    float e0 = expf(s0 - m), e1 = expf(s1 - m);
    g_attn[0] = e0 / (e0 + e1);
    g_attn[1] = e1 / (e0 + e1);
}

__global__ void combine_kernel() {
    int i = blockIdx.x * blockDim.x + threadIdx.x;
    if (i >= NADDR*HID) return;
    float v = g_attn[0]*g_accA1[i] + g_attn[1]*g_accA2[i];
    g_bufA[i] = v > 0.f ? v : 0.f;
}

// ---------------- final linear ------------------------------------------------------
__global__ void final_kernel(const float* __restrict__ W, const float* __restrict__ b,
                             float* __restrict__ out) {
    int n = blockIdx.x * blockDim.x + threadIdx.x;
    if (n >= NADDR) return;
    float a0 = b[0], a1 = b[1];
    const float* ar = g_bufA + (long)n*HID;
    #pragma unroll
    for (int k = 0; k < HID; k++) {
        float v = ar[k];
        a0 = fmaf(v, W[k*2],     a0);
        a1 = fmaf(v, W[k*2 + 1], a1);
    }
    out[n*2] = a0;
    out[n*2 + 1] = a1;
}

// ---------------- host orchestration ------------------------------------------------
static void build_csr(int rel, const int* src, const int* dst, int Nd, int E) {
    int B = (Nd + 1023) / 1024;
    zero_cnt_kernel<<<(Nd + 255)/256, 256>>>(Nd);
    count_kernel<<<(E + 255)/256, 256>>>(dst, E);
    scan1_kernel<<<B, 256>>>(rel, Nd);
    scan2_kernel<<<1, 256>>>(B);
    scan3_kernel<<<(Nd + 255)/256, 256>>>(rel, Nd, E);
    scatter_kernel<<<(E + 255)/256, 256>>>(rel, src, dst, E);
}

extern "C" void kernel_launch(void* const* d_in, const int* in_sizes, int n_in,
                              void* d_out, int out_size) {
    const float* x_addr  = (const float*)d_in[0];
    const float* x_tx    = (const float*)d_in[1];
    const int*   eat_s   = (const int*)d_in[2];
    const int*   eat_d   = (const int*)d_in[3];
    const int*   eta_s   = (const int*)d_in[4];
    const int*   eta_d   = (const int*)d_in[5];
    const int*   eaa_s   = (const int*)d_in[6];
    const int*   eaa_d   = (const int*)d_in[7];
    const float* pW1     = (const float*)d_in[8];
    const float* pb1     = (const float*)d_in[9];
    const float* pW23    = (const float*)d_in[10];
    const float* pb23    = (const float*)d_in[11];
    const float* att_src = (const float*)d_in[12];
    const float* att_dst = (const float*)d_in[13];
    const float* kW      = (const float*)d_in[14];
    const float* kb      = (const float*)d_in[15];
    const float* q       = (const float*)d_in[16];
    const float* linW    = (const float*)d_in[17];
    const float* linb    = (const float*)d_in[18];

    // CSR built once per launch (edge lists are layer-invariant)
    build_csr(0, eat_s, eat_d, NTX,   EAT);
    build_csr(1, eta_s, eta_d, NADDR, ETA);
    build_csr(2, eaa_s, eaa_d, NADDR, EAA);

    for (int l = 0; l < 3; l++) {
        const float *Wa, *ba, *Wt, *bt;
        int IN, in_a, in_t;
        if (l == 0) {
            Wa = pW1;               ba = pb1;
            Wt = pW1 + INDIM*HID;   bt = pb1 + HID;
            IN = INDIM; in_a = 0; in_t = 0;
        } else {
            Wa = pW23 + ((l-1)*2 + 0)*HID*HID;  ba = pb23 + ((l-1)*2 + 0)*HID;
            Wt = pW23 + ((l-1)*2 + 1)*HID*HID;  bt = pb23 + ((l-1)*2 + 1)*HID;
            IN = HID; in_a = 1; in_t = 2;
        }
        lin_kernel<<<(NADDR + 7)/8, 256>>>(in_a, x_addr, Wa, ba, 0, NADDR, IN);
        lin_kernel<<<(NTX   + 7)/8, 256>>>(in_t, x_tx,   Wt, bt, 1, NTX,   IN);

        const float* As = att_src + (l*3) * HEADS * 8;
        const float* Ad = att_dst + (l*3) * HEADS * 8;
        alpha_addr_kernel<<<(NADDR*HEADS + 255)/256, 256>>>(As + 0*32, Ad + 1*32,
                                                            As + 2*32, Ad + 2*32);
        alpha_tx_kernel<<<(NTX*HEADS + 255)/256, 256>>>(Ad + 0*32, As + 1*32);

        agg_kernel<<<(NTX   + 7)/8, 256>>>(0);
        agg_kernel<<<(NADDR + 7)/8, 256>>>(1);
        agg_kernel<<<(NADDR + 7)/8, 256>>>(2);

        zero_tacc_kernel<<<1, 64>>>();
        sem_mean_kernel<<<(NADDR + 255)/256, 256>>>(0, kW + l*HID*HID, kb + l*HID);
        sem_mean_kernel<<<(NADDR + 255)/256, 256>>>(1, kW + l*HID*HID, kb + l*HID);
        attn_kernel<<<1, 1>>>(q + l*HID);
        combine_kernel<<<(NADDR*HID + 255)/256, 256>>>();
    }
    final_kernel<<<(NADDR + 255)/256, 256>>>(linW, linb, (float*)d_out);
}

// round 7
// speedup vs baseline: 1.7031x; 1.0726x over previous
#include <cuda_runtime.h>

#define NADDR 150000
#define NTX   200000
#define INDIM 64
#define HID   32
#define HEADS 4
#define EAT   1000000
#define ETA   1000000
#define EAA   500000

// block partitions
#define NB_A   18750            // ceil(NADDR/8)
#define NB_T   25000            // ceil(NTX/8)
#define SB0    196              // ceil(NTX/1024)
#define SB1    147              // ceil(NADDR/1024)
#define SB2    147

// ---------------- scratch (static device globals) -----------------------------------
__device__ float g_hA[NADDR*HID];
__device__ float g_hT[NTX*HID];
__device__ float g_accT[NTX*HID];
__device__ float g_accA1[NADDR*HID];
__device__ float g_accA2[NADDR*HID];
__device__ float g_bufA[NADDR*HID];
__device__ float g_as0[NADDR*HEADS];
__device__ float g_ad1[NADDR*HEADS];
__device__ float g_as2[NADDR*HEADS];
__device__ float g_ad2[NADDR*HEADS];
__device__ float g_tad0[NTX*HEADS];
__device__ float g_tas1[NTX*HEADS];
__device__ float g_tacc[2*HID];
__device__ float g_attn[2];

__device__ int g_offsT[NTX + 1];
__device__ int g_offsA1[NADDR + 1];
__device__ int g_offsA2[NADDR + 1];
__device__ int g_csr0[EAT];
__device__ int g_csr1[ETA];
__device__ int g_csr2[EAA];
__device__ int g_cnt0[NTX];
__device__ int g_cnt1[NADDR];
__device__ int g_cnt2[NADDR];
__device__ int g_cur0[NTX];
__device__ int g_cur1[NADDR];
__device__ int g_cur2[NADDR];
__device__ int g_bs0[256];
__device__ int g_bs1[256];
__device__ int g_bs2[256];

__device__ __forceinline__ float fast_tanh(float x) {
    return 1.f - __fdividef(2.f, __expf(2.f * x) + 1.f);
}

// ---------------- CSR build (all 3 relations per launch) -----------------------------
__global__ void csr_zero_kernel() {
    int i = blockIdx.x * blockDim.x + threadIdx.x;
    if (i < NTX)   g_cnt0[i] = 0;
    if (i < NADDR) { g_cnt1[i] = 0; g_cnt2[i] = 0; }
}
__global__ void csr_count_kernel(const int* __restrict__ d0, const int* __restrict__ d1,
                                 const int* __restrict__ d2) {
    int e = blockIdx.x * blockDim.x + threadIdx.x;
    if (e < EAT) atomicAdd(&g_cnt0[d0[e]], 1);
    if (e < ETA) atomicAdd(&g_cnt1[d1[e]], 1);
    if (e < EAA) atomicAdd(&g_cnt2[d2[e]], 1);
}
__global__ void csr_scan1_kernel() {
    __shared__ int ts[256];
    int b = blockIdx.x;
    const int* cnt; int* offs; int* bs; int N; int lb;
    if (b < SB0)            { cnt = g_cnt0; offs = g_offsT;  bs = g_bs0; N = NTX;   lb = b; }
    else if (b < SB0 + SB1) { cnt = g_cnt1; offs = g_offsA1; bs = g_bs1; N = NADDR; lb = b - SB0; }
    else                    { cnt = g_cnt2; offs = g_offsA2; bs = g_bs2; N = NADDR; lb = b - SB0 - SB1; }
    int tid = threadIdx.x;
    int base = lb * 1024;
    int v[4]; int sum = 0;
    #pragma unroll
    for (int j = 0; j < 4; j++) {
        int idx = base + tid * 4 + j;
        v[j] = (idx < N) ? cnt[idx] : 0;
        sum += v[j];
    }
    ts[tid] = sum;
    __syncthreads();
    for (int off = 1; off < 256; off <<= 1) {
        int t = (tid >= off) ? ts[tid - off] : 0;
        __syncthreads();
        ts[tid] += t;
        __syncthreads();
    }
    int run = ts[tid] - sum;
    #pragma unroll
    for (int j = 0; j < 4; j++) {
        int idx = base + tid * 4 + j;
        if (idx < N) offs[idx] = run;
        run += v[j];
    }
    if (tid == 255) bs[lb] = ts[255];
}
__global__ void csr_scan2_kernel() {
    __shared__ int ts[256];
    int tid = threadIdx.x;
    for (int r = 0; r < 3; r++) {
        int* bs = r == 0 ? g_bs0 : (r == 1 ? g_bs1 : g_bs2);
        int B   = r == 0 ? SB0  : (r == 1 ? SB1  : SB2);
        int v = (tid < B) ? bs[tid] : 0;
        ts[tid] = v;
        __syncthreads();
        for (int off = 1; off < 256; off <<= 1) {
            int t = (tid >= off) ? ts[tid - off] : 0;
            __syncthreads();
            ts[tid] += t;
            __syncthreads();
        }
        if (tid < B) bs[tid] = ts[tid] - v;
        __syncthreads();
    }
}
__global__ void csr_scan3_kernel() {
    int i = blockIdx.x * blockDim.x + threadIdx.x;
    if (i < NTX) {
        int o = g_offsT[i] + g_bs0[i >> 10];
        g_offsT[i] = o; g_cur0[i] = o;
    }
    if (i < NADDR) {
        int o = g_offsA1[i] + g_bs1[i >> 10];
        g_offsA1[i] = o; g_cur1[i] = o;
        o = g_offsA2[i] + g_bs2[i >> 10];
        g_offsA2[i] = o; g_cur2[i] = o;
    }
    if (i == 0) { g_offsT[NTX] = EAT; g_offsA1[NADDR] = ETA; g_offsA2[NADDR] = EAA; }
}
__global__ void csr_scatter_kernel(const int* __restrict__ s0, const int* __restrict__ d0,
                                   const int* __restrict__ s1, const int* __restrict__ d1,
                                   const int* __restrict__ s2, const int* __restrict__ d2) {
    int e = blockIdx.x * blockDim.x + threadIdx.x;
    if (e < EAT) { int p = atomicAdd(&g_cur0[d0[e]], 1); g_csr0[p] = s0[e]; }
    if (e < ETA) { int p = atomicAdd(&g_cur1[d1[e]], 1); g_csr1[p] = s1[e]; }
    if (e < EAA) { int p = atomicAdd(&g_cur2[d2[e]], 1); g_csr2[p] = s2[e]; }
}

// ---------------- fused linear projection + per-head attention dots ------------------
// warp = node; lane j = output feature. Alphas via width-8 shuffle reductions.
__global__ void __launch_bounds__(256) lin_alpha_kernel(
        int l, const float* __restrict__ xa_ext, const float* __restrict__ xt_ext,
        const float* __restrict__ Wa, const float* __restrict__ ba,
        const float* __restrict__ Wt, const float* __restrict__ bt,
        const float* __restrict__ As, const float* __restrict__ Ad, int IN) {
    __shared__ float Ws[INDIM*HID];
    __shared__ float Att[4*HID];
    bool is_addr = blockIdx.x < NB_A;
    int tid = threadIdx.x;

    if (blockIdx.x == 0 && tid < 2*HID) g_tacc[tid] = 0.f;   // zero semantic accum

    const float* W = is_addr ? Wa : Wt;
    for (int i = tid; i < IN*HID; i += 256) Ws[i] = W[i];
    if (is_addr) {
        if (tid < HID)       Att[tid]         = As[tid];             // as0
        else if (tid < 2*HID) Att[tid]        = Ad[HID + (tid-HID)]; // ad1
        else if (tid < 3*HID) Att[tid]        = As[2*HID + (tid-2*HID)]; // as2
        else if (tid < 4*HID) Att[tid]        = Ad[2*HID + (tid-3*HID)]; // ad2
    } else {
        if (tid < HID)        Att[tid]        = Ad[tid];             // tad0
        else if (tid < 2*HID) Att[tid]        = As[HID + (tid-HID)]; // tas1
    }
    __syncthreads();

    int slot = tid >> 5, j = tid & 31;
    int n = (is_addr ? blockIdx.x : blockIdx.x - NB_A) * 8 + slot;
    int N = is_addr ? NADDR : NTX;
    if (n >= N) return;

    const float* x = is_addr ? (l == 0 ? xa_ext : (const float*)g_bufA)
                             : (l == 0 ? xt_ext : (const float*)g_accT);
    const float* bb = is_addr ? ba : bt;
    const float* xr = x + (long)n * IN;
    float acc = bb[j];
    #pragma unroll 8
    for (int k = 0; k < IN; k++) acc = fmaf(xr[k], Ws[k*HID + j], acc);

    float* y = is_addr ? g_hA : g_hT;
    y[(long)n*HID + j] = acc;

    int grp = j >> 3;
    unsigned m = 0xffffffffu;
    if (is_addr) {
        float p0 = acc * Att[j], p1 = acc * Att[HID + j];
        float p2 = acc * Att[2*HID + j], p3 = acc * Att[3*HID + j];
        #pragma unroll
        for (int o = 4; o >= 1; o >>= 1) {
            p0 += __shfl_xor_sync(m, p0, o);
            p1 += __shfl_xor_sync(m, p1, o);
            p2 += __shfl_xor_sync(m, p2, o);
            p3 += __shfl_xor_sync(m, p3, o);
        }
        if ((j & 7) == 0) {
            g_as0[n*4 + grp] = p0; g_ad1[n*4 + grp] = p1;
            g_as2[n*4 + grp] = p2; g_ad2[n*4 + grp] = p3;
        }
    } else {
        float p0 = acc * Att[j], p1 = acc * Att[HID + j];
        #pragma unroll
        for (int o = 4; o >= 1; o >>= 1) {
            p0 += __shfl_xor_sync(m, p0, o);
            p1 += __shfl_xor_sync(m, p1, o);
        }
        if ((j & 7) == 0) {
            g_tad0[n*4 + grp] = p0; g_tas1[n*4 + grp] = p1;
        }
    }
}

// ---------------- gather aggregation: all 3 relations, warp-per-node, unroll-4 -------
__global__ void __launch_bounds__(256) agg_kernel() {
    int b = blockIdx.x;
    const int *offs, *csr;
    const float *asv, *adv, *hs;
    float* out;
    int N, nb;
    if (b < NB_T) {
        offs = g_offsT;  csr = g_csr0; asv = g_as0;  adv = g_tad0;
        hs = g_hA; out = g_accT;  N = NTX;   nb = b;
    } else if (b < NB_T + NB_A) {
        offs = g_offsA1; csr = g_csr1; asv = g_tas1; adv = g_ad1;
        hs = g_hT; out = g_accA1; N = NADDR; nb = b - NB_T;
    } else {
        offs = g_offsA2; csr = g_csr2; asv = g_as2;  adv = g_ad2;
        hs = g_hA; out = g_accA2; N = NADDR; nb = b - NB_T - NB_A;
    }
    int n = nb * 8 + (threadIdx.x >> 5);
    if (n >= N) return;
    int lane = threadIdx.x & 31;
    int h = lane >> 3;
    float ad = __ldg(adv + n*4 + h);
    int beg = __ldg(offs + n), end = __ldg(offs + n + 1);
    float acc = 0.f, den = 0.f;
    int k = beg;
    for (; k + 4 <= end; k += 4) {
        int s0 = __ldg(csr + k),     s1 = __ldg(csr + k + 1);
        int s2 = __ldg(csr + k + 2), s3 = __ldg(csr + k + 3);
        float a0 = __ldg(asv + s0*4 + h), a1 = __ldg(asv + s1*4 + h);
        float a2 = __ldg(asv + s2*4 + h), a3 = __ldg(asv + s3*4 + h);
        float r0 = __ldg(hs + ((long)s0 << 5) + lane);
        float r1 = __ldg(hs + ((long)s1 << 5) + lane);
        float r2 = __ldg(hs + ((long)s2 << 5) + lane);
        float r3 = __ldg(hs + ((long)s3 << 5) + lane);
        a0 += ad; a1 += ad; a2 += ad; a3 += ad;
        a0 = fmaxf(a0, 0.2f*a0); a1 = fmaxf(a1, 0.2f*a1);   // leaky_relu (slope<1)
        a2 = fmaxf(a2, 0.2f*a2); a3 = fmaxf(a3, 0.2f*a3);
        float e0 = __expf(a0), e1 = __expf(a1), e2 = __expf(a2), e3 = __expf(a3);
        den += (e0 + e1) + (e2 + e3);
        acc = fmaf(e0, r0, acc); acc = fmaf(e1, r1, acc);
        acc = fmaf(e2, r2, acc); acc = fmaf(e3, r3, acc);
    }
    for (; k < end; k++) {
        int s = __ldg(csr + k);
        float l = __ldg(asv + s*4 + h) + ad;
        l = fmaxf(l, 0.2f*l);
        float ev = __expf(l);
        den += ev;
        acc = fmaf(ev, __ldg(hs + ((long)s << 5) + lane), acc);
    }
    float v = acc / (den + 1e-16f);
    out[(long)n*HID + lane] = fmaxf(v, 0.f);
}

// ---------------- semantic attention (both relations fused) --------------------------
__global__ void __launch_bounds__(256) sem_kernel(const float* __restrict__ kW,
                                                  const float* __restrict__ kb) {
    __shared__ float Ws[HID*HID];
    __shared__ float red1[256], red2[256];
    int tid = threadIdx.x;
    for (int i = tid; i < HID*HID; i += 256) Ws[i] = kW[i];
    __syncthreads();
    int j = tid & 31, slot = tid >> 5;
    float bj = kb[j];
    float a1 = 0.f, a2 = 0.f;
    int n0 = blockIdx.x * 256 + slot;
    for (int it = 0; it < 32; it++) {
        int n = n0 + it*8;
        if (n < NADDR) {
            const float* r1 = g_accA1 + (long)n*HID;
            const float* r2 = g_accA2 + (long)n*HID;
            float d1 = bj, d2 = bj;
            #pragma unroll
            for (int k = 0; k < HID; k++) {
                float w = Ws[k*HID + j];
                d1 = fmaf(r1[k], w, d1);
                d2 = fmaf(r2[k], w, d2);
            }
            a1 += fast_tanh(d1);
            a2 += fast_tanh(d2);
        }
    }
    red1[tid] = a1; red2[tid] = a2;
    __syncthreads();
    if (slot == 0) {
        float s1 = 0.f, s2 = 0.f;
        #pragma unroll
        for (int ss = 0; ss < 8; ss++) { s1 += red1[ss*32 + j]; s2 += red2[ss*32 + j]; }
        atomicAdd(&g_tacc[j], s1);
        atomicAdd(&g_tacc[HID + j], s2);
    }
}

__global__ void attn_kernel(const float* __restrict__ q) {
    const float invN = 1.f / (float)NADDR;
    float s0 = 0.f, s1 = 0.f;
    for (int j = 0; j < HID; j++) {
        s0 += g_tacc[j] * invN * q[j];
        s1 += g_tacc[HID + j] * invN * q[j];
    }
    float m = fmaxf(s0, s1);
    float e0 = expf(s0 - m), e1 = expf(s1 - m);
    g_attn[0] = e0 / (e0 + e1);
    g_attn[1] = e1 / (e0 + e1);
}

__global__ void combine_kernel() {
    int i = blockIdx.x * blockDim.x + threadIdx.x;
    if (i >= NADDR*HID) return;
    float v = g_attn[0]*g_accA1[i] + g_attn[1]*g_accA2[i];
    g_bufA[i] = v > 0.f ? v : 0.f;
}

__global__ void final_kernel(const float* __restrict__ W, const float* __restrict__ b,
                             float* __restrict__ out) {
    int n = blockIdx.x * blockDim.x + threadIdx.x;
    if (n >= NADDR) return;
    float a0 = b[0], a1 = b[1];
    const float* ar = g_bufA + (long)n*HID;
    #pragma unroll
    for (int k = 0; k < HID; k++) {
        float v = ar[k];
        a0 = fmaf(v, W[k*2],     a0);
        a1 = fmaf(v, W[k*2 + 1], a1);
    }
    out[n*2] = a0;
    out[n*2 + 1] = a1;
}

// ---------------- host orchestration -------------------------------------------------
extern "C" void kernel_launch(void* const* d_in, const int* in_sizes, int n_in,
                              void* d_out, int out_size) {
    const float* x_addr  = (const float*)d_in[0];
    const float* x_tx    = (const float*)d_in[1];
    const int*   eat_s   = (const int*)d_in[2];
    const int*   eat_d   = (const int*)d_in[3];
    const int*   eta_s   = (const int*)d_in[4];
    const int*   eta_d   = (const int*)d_in[5];
    const int*   eaa_s   = (const int*)d_in[6];
    const int*   eaa_d   = (const int*)d_in[7];
    const float* pW1     = (const float*)d_in[8];
    const float* pb1     = (const float*)d_in[9];
    const float* pW23    = (const float*)d_in[10];
    const float* pb23    = (const float*)d_in[11];
    const float* att_src = (const float*)d_in[12];
    const float* att_dst = (const float*)d_in[13];
    const float* kW      = (const float*)d_in[14];
    const float* kb      = (const float*)d_in[15];
    const float* q       = (const float*)d_in[16];
    const float* linW    = (const float*)d_in[17];
    const float* linb    = (const float*)d_in[18];

    // CSR build (all 3 relations; 6 launches)
    csr_zero_kernel<<<(NTX + 255)/256, 256>>>();
    csr_count_kernel<<<(EAT + 255)/256, 256>>>(eat_d, eta_d, eaa_d);
    csr_scan1_kernel<<<SB0 + SB1 + SB2, 256>>>();
    csr_scan2_kernel<<<1, 256>>>();
    csr_scan3_kernel<<<(NTX + 255)/256, 256>>>();
    csr_scatter_kernel<<<(EAT + 255)/256, 256>>>(eat_s, eat_d, eta_s, eta_d, eaa_s, eaa_d);

    for (int l = 0; l < 3; l++) {
        const float *Wa, *ba, *Wt, *bt;
        int IN;
        if (l == 0) {
            Wa = pW1;               ba = pb1;
            Wt = pW1 + INDIM*HID;   bt = pb1 + HID;
            IN = INDIM;
        } else {
            Wa = pW23 + ((l-1)*2 + 0)*HID*HID;  ba = pb23 + ((l-1)*2 + 0)*HID;
            Wt = pW23 + ((l-1)*2 + 1)*HID*HID;  bt = pb23 + ((l-1)*2 + 1)*HID;
            IN = HID;
        }
        const float* As = att_src + (l*3) * HEADS * 8;
        const float* Ad = att_dst + (l*3) * HEADS * 8;

        lin_alpha_kernel<<<NB_A + NB_T, 256>>>(l, x_addr, x_tx, Wa, ba, Wt, bt, As, Ad, IN);
        agg_kernel<<<NB_T + NB_A + NB_A, 256>>>();
        sem_kernel<<<(NADDR + 255)/256, 256>>>(kW + l*HID*HID, kb + l*HID);
        attn_kernel<<<1, 1>>>(q + l*HID);
        combine_kernel<<<(NADDR*HID + 255)/256, 256>>>();
    }
    final_kernel<<<(NADDR + 255)/256, 256>>>(linW, linb, (float*)d_out);
}

// round 8
// speedup vs baseline: 1.7516x; 1.0285x over previous
#include <cuda_runtime.h>

#define NADDR 150000
#define NTX   200000
#define INDIM 64
#define HID   32
#define HEADS 4
#define EAT   1000000
#define ETA   1000000
#define EAA   500000

// block partitions
#define NB_A   18750            // NADDR/8 (exact)
#define NB_T   25000            // NTX/8   (exact)
#define SB0    196              // ceil(NTX/1024)
#define SB1    147              // ceil(NADDR/1024)
#define SB2    147

// ---------------- scratch (static device globals) -----------------------------------
__device__ float g_hA[NADDR*HID];
__device__ float g_hT[NTX*HID];
__device__ float g_accT[NTX*HID];
__device__ float g_accA1[NADDR*HID];
__device__ float g_accA2[NADDR*HID];
__device__ float g_as0[NADDR*HEADS];
__device__ float g_ad1[NADDR*HEADS];
__device__ float g_as2[NADDR*HEADS];
__device__ float g_ad2[NADDR*HEADS];
__device__ float g_tad0[NTX*HEADS];
__device__ float g_tas1[NTX*HEADS];
__device__ float g_tacc[2*64];         // double-buffered semantic accumulators (parity = layer&1)

__device__ int g_offsT[NTX + 1];
__device__ int g_offsA1[NADDR + 1];
__device__ int g_offsA2[NADDR + 1];
__device__ int g_csr0[EAT];
__device__ int g_csr1[ETA];
__device__ int g_csr2[EAA];
__device__ int g_cnt0[NTX];            // zero-initialized; scan1 re-zeroes after read
__device__ int g_cnt1[NADDR];
__device__ int g_cnt2[NADDR];
__device__ int g_cur0[NTX];
__device__ int g_cur1[NADDR];
__device__ int g_cur2[NADDR];
__device__ int g_bs0[256];
__device__ int g_bs1[256];
__device__ int g_bs2[256];

__device__ __forceinline__ float fast_tanh(float x) {
    return 1.f - __fdividef(2.f, __expf(2.f * x) + 1.f);
}

// ---------------- CSR build (4 launches total) ---------------------------------------
__global__ void csr_count_kernel(const int* __restrict__ d0, const int* __restrict__ d1,
                                 const int* __restrict__ d2) {
    int e = blockIdx.x * blockDim.x + threadIdx.x;
    if (e < EAT) atomicAdd(&g_cnt0[d0[e]], 1);
    if (e < ETA) atomicAdd(&g_cnt1[d1[e]], 1);
    if (e < EAA) atomicAdd(&g_cnt2[d2[e]], 1);
}
// per-1024-chunk exclusive scan; zeroes cnt after reading (ready for next invocation)
__global__ void csr_scan1_kernel() {
    __shared__ int ts[256];
    int b = blockIdx.x;
    int* cnt; int* offs; int* bs; int N; int lb;
    if (b < SB0)            { cnt = g_cnt0; offs = g_offsT;  bs = g_bs0; N = NTX;   lb = b; }
    else if (b < SB0 + SB1) { cnt = g_cnt1; offs = g_offsA1; bs = g_bs1; N = NADDR; lb = b - SB0; }
    else                    { cnt = g_cnt2; offs = g_offsA2; bs = g_bs2; N = NADDR; lb = b - SB0 - SB1; }
    int tid = threadIdx.x;
    int base = lb * 1024;
    int v[4]; int sum = 0;
    #pragma unroll
    for (int j = 0; j < 4; j++) {
        int idx = base + tid * 4 + j;
        v[j] = (idx < N) ? cnt[idx] : 0;
        if (idx < N) cnt[idx] = 0;          // reset for next graph replay
        sum += v[j];
    }
    ts[tid] = sum;
    __syncthreads();
    for (int off = 1; off < 256; off <<= 1) {
        int t = (tid >= off) ? ts[tid - off] : 0;
        __syncthreads();
        ts[tid] += t;
        __syncthreads();
    }
    int run = ts[tid] - sum;
    #pragma unroll
    for (int j = 0; j < 4; j++) {
        int idx = base + tid * 4 + j;
        if (idx < N) offs[idx] = run;
        run += v[j];
    }
    if (tid == 255) bs[lb] = ts[255];
}
// adds block-sum prefixes (computed locally from smem) and initializes cursors
__global__ void csr_scan3_kernel() {
    __shared__ int sb0[SB0], sb1[SB1], sb2[SB2];
    int tid = threadIdx.x;
    for (int i = tid; i < SB0; i += 256) sb0[i] = g_bs0[i];
    for (int i = tid; i < SB1; i += 256) sb1[i] = g_bs1[i];
    for (int i = tid; i < SB2; i += 256) sb2[i] = g_bs2[i];
    __syncthreads();
    int i = blockIdx.x * 256 + tid;
    if (i < NTX) {
        int lb = i >> 10, pre = 0;
        for (int k = 0; k < lb; k++) pre += sb0[k];
        int o = g_offsT[i] + pre;
        g_offsT[i] = o; g_cur0[i] = o;
    }
    if (i < NADDR) {
        int lb = i >> 10, p1 = 0, p2 = 0;
        for (int k = 0; k < lb; k++) { p1 += sb1[k]; p2 += sb2[k]; }
        int o = g_offsA1[i] + p1;
        g_offsA1[i] = o; g_cur1[i] = o;
        o = g_offsA2[i] + p2;
        g_offsA2[i] = o; g_cur2[i] = o;
    }
    if (i == 0) { g_offsT[NTX] = EAT; g_offsA1[NADDR] = ETA; g_offsA2[NADDR] = EAA; }
}
__global__ void csr_scatter_kernel(const int* __restrict__ s0, const int* __restrict__ d0,
                                   const int* __restrict__ s1, const int* __restrict__ d1,
                                   const int* __restrict__ s2, const int* __restrict__ d2) {
    int e = blockIdx.x * blockDim.x + threadIdx.x;
    if (e < EAT) { int p = atomicAdd(&g_cur0[d0[e]], 1); g_csr0[p] = s0[e]; }
    if (e < ETA) { int p = atomicAdd(&g_cur1[d1[e]], 1); g_csr1[p] = s1[e]; }
    if (e < EAA) { int p = atomicAdd(&g_cur2[d2[e]], 1); g_csr2[p] = s2[e]; }
}

// ---------------- fused: [semantic combine] + linear projection + attention dots -----
// warp = node; lane j = output feature. For l>0 the addr input row is formed on the
// fly as relu(attn0*accA1 + attn1*accA2); attn weights recomputed per block from tacc.
__global__ void __launch_bounds__(256) lin_alpha_kernel(
        int l, const float* __restrict__ xa_ext, const float* __restrict__ xt_ext,
        const float* __restrict__ Wa, const float* __restrict__ ba,
        const float* __restrict__ Wt, const float* __restrict__ bt,
        const float* __restrict__ As, const float* __restrict__ Ad,
        const float* __restrict__ q_prev, int IN) {
    __shared__ float Ws[INDIM*HID];
    __shared__ float Att[4*HID];
    __shared__ float sAttn[2];
    bool is_addr = blockIdx.x < NB_A;
    int tid = threadIdx.x;

    // zero this layer's semantic accumulator buffer (parity l&1); consumers of the
    // previous layer read parity (l-1)&1 — different buffer, no race.
    if (blockIdx.x == 0 && tid < 64) g_tacc[(l & 1) * 64 + tid] = 0.f;

    const float* W = is_addr ? Wa : Wt;
    for (int i = tid; i < IN*HID; i += 256) Ws[i] = W[i];
    if (is_addr) {
        if (tid < HID)        Att[tid] = As[tid];                    // as0
        else if (tid < 2*HID) Att[tid] = Ad[HID + (tid-HID)];        // ad1
        else if (tid < 3*HID) Att[tid] = As[2*HID + (tid-2*HID)];    // as2
        else if (tid < 4*HID) Att[tid] = Ad[2*HID + (tid-3*HID)];    // ad2
    } else {
        if (tid < HID)        Att[tid] = Ad[tid];                    // tad0
        else if (tid < 2*HID) Att[tid] = As[HID + (tid-HID)];        // tas1
    }
    if (l > 0 && tid < 32) {       // semantic attention weights of previous layer
        int prev = (l - 1) & 1;
        float qv = q_prev[tid];
        float p0 = g_tacc[prev*64 + tid] * qv;
        float p1 = g_tacc[prev*64 + 32 + tid] * qv;
        #pragma unroll
        for (int o = 16; o >= 1; o >>= 1) {
            p0 += __shfl_xor_sync(0xffffffffu, p0, o);
            p1 += __shfl_xor_sync(0xffffffffu, p1, o);
        }
        if (tid == 0) {
            float s0 = p0 * (1.f / NADDR), s1 = p1 * (1.f / NADDR);
            float m = fmaxf(s0, s1);
            float e0 = __expf(s0 - m), e1 = __expf(s1 - m);
            sAttn[0] = e0 / (e0 + e1);
            sAttn[1] = e1 / (e0 + e1);
        }
    }
    __syncthreads();

    int slot = tid >> 5, j = tid & 31;
    int n = (is_addr ? blockIdx.x : blockIdx.x - NB_A) * 8 + slot;

    float acc = is_addr ? ba[j] : bt[j];
    if (l == 0) {
        const float* xr = (is_addr ? xa_ext : xt_ext) + (long)n * IN;
        #pragma unroll 8
        for (int k = 0; k < IN; k++) acc = fmaf(xr[k], Ws[k*HID + j], acc);
    } else {
        // lane owns one input feature; distribute via shuffle
        float c;
        if (is_addr) {
            float a1 = g_accA1[(long)n*HID + j];
            float a2 = g_accA2[(long)n*HID + j];
            c = fmaxf(sAttn[0]*a1 + sAttn[1]*a2, 0.f);
        } else {
            c = g_accT[(long)n*HID + j];
        }
        #pragma unroll
        for (int k = 0; k < HID; k++)
            acc = fmaf(__shfl_sync(0xffffffffu, c, k), Ws[k*HID + j], acc);
    }

    float* y = is_addr ? g_hA : g_hT;
    y[(long)n*HID + j] = acc;

    int grp = j >> 3;
    unsigned m = 0xffffffffu;
    if (is_addr) {
        float p0 = acc * Att[j],       p1 = acc * Att[HID + j];
        float p2 = acc * Att[2*HID+j], p3 = acc * Att[3*HID + j];
        #pragma unroll
        for (int o = 4; o >= 1; o >>= 1) {
            p0 += __shfl_xor_sync(m, p0, o);
            p1 += __shfl_xor_sync(m, p1, o);
            p2 += __shfl_xor_sync(m, p2, o);
            p3 += __shfl_xor_sync(m, p3, o);
        }
        if ((j & 7) == 0) {
            g_as0[n*4 + grp] = p0; g_ad1[n*4 + grp] = p1;
            g_as2[n*4 + grp] = p2; g_ad2[n*4 + grp] = p3;
        }
    } else {
        float p0 = acc * Att[j], p1 = acc * Att[HID + j];
        #pragma unroll
        for (int o = 4; o >= 1; o >>= 1) {
            p0 += __shfl_xor_sync(m, p0, o);
            p1 += __shfl_xor_sync(m, p1, o);
        }
        if ((j & 7) == 0) {
            g_tad0[n*4 + grp] = p0; g_tas1[n*4 + grp] = p1;
        }
    }
}

// ---------------- gather aggregation: all 3 relations, warp-per-node, unroll-4 -------
__global__ void __launch_bounds__(256) agg_kernel() {
    int b = blockIdx.x;
    const int *offs, *csr;
    const float *asv, *adv, *hs;
    float* out;
    int nb;
    if (b < NB_T) {
        offs = g_offsT;  csr = g_csr0; asv = g_as0;  adv = g_tad0;
        hs = g_hA; out = g_accT;  nb = b;
    } else if (b < NB_T + NB_A) {
        offs = g_offsA1; csr = g_csr1; asv = g_tas1; adv = g_ad1;
        hs = g_hT; out = g_accA1; nb = b - NB_T;
    } else {
        offs = g_offsA2; csr = g_csr2; asv = g_as2;  adv = g_ad2;
        hs = g_hA; out = g_accA2; nb = b - NB_T - NB_A;
    }
    int n = nb * 8 + (threadIdx.x >> 5);
    int lane = threadIdx.x & 31;
    int h = lane >> 3;
    float ad = __ldg(adv + n*4 + h);
    int beg = __ldg(offs + n), end = __ldg(offs + n + 1);
    float acc = 0.f, den = 0.f;
    int k = beg;
    for (; k + 4 <= end; k += 4) {
        int s0 = __ldg(csr + k),     s1 = __ldg(csr + k + 1);
        int s2 = __ldg(csr + k + 2), s3 = __ldg(csr + k + 3);
        float a0 = __ldg(asv + s0*4 + h), a1 = __ldg(asv + s1*4 + h);
        float a2 = __ldg(asv + s2*4 + h), a3 = __ldg(asv + s3*4 + h);
        float r0 = __ldg(hs + ((long)s0 << 5) + lane);
        float r1 = __ldg(hs + ((long)s1 << 5) + lane);
        float r2 = __ldg(hs + ((long)s2 << 5) + lane);
        float r3 = __ldg(hs + ((long)s3 << 5) + lane);
        a0 += ad; a1 += ad; a2 += ad; a3 += ad;
        a0 = fmaxf(a0, 0.2f*a0); a1 = fmaxf(a1, 0.2f*a1);   // leaky_relu (slope<1)
        a2 = fmaxf(a2, 0.2f*a2); a3 = fmaxf(a3, 0.2f*a3);
        float e0 = __expf(a0), e1 = __expf(a1), e2 = __expf(a2), e3 = __expf(a3);
        den += (e0 + e1) + (e2 + e3);
        acc = fmaf(e0, r0, acc); acc = fmaf(e1, r1, acc);
        acc = fmaf(e2, r2, acc); acc = fmaf(e3, r3, acc);
    }
    for (; k < end; k++) {
        int s = __ldg(csr + k);
        float l = __ldg(asv + s*4 + h) + ad;
        l = fmaxf(l, 0.2f*l);
        float ev = __expf(l);
        den += ev;
        acc = fmaf(ev, __ldg(hs + ((long)s << 5) + lane), acc);
    }
    float v = acc / (den + 1e-16f);
    out[(long)n*HID + lane] = fmaxf(v, 0.f);
}

// ---------------- semantic attention mean (both relations, into parity buffer) ------
__global__ void __launch_bounds__(256) sem_kernel(const float* __restrict__ kW,
                                                  const float* __restrict__ kb, int par) {
    __shared__ float Ws[HID*HID];
    __shared__ float red1[256], red2[256];
    int tid = threadIdx.x;
    for (int i = tid; i < HID*HID; i += 256) Ws[i] = kW[i];
    __syncthreads();
    int j = tid & 31, slot = tid >> 5;
    float bj = kb[j];
    float a1 = 0.f, a2 = 0.f;
    int n0 = blockIdx.x * 256 + slot;
    for (int it = 0; it < 32; it++) {
        int n = n0 + it*8;
        if (n < NADDR) {
            const float* r1 = g_accA1 + (long)n*HID;
            const float* r2 = g_accA2 + (long)n*HID;
            float d1 = bj, d2 = bj;
            #pragma unroll
            for (int k = 0; k < HID; k++) {
                float w = Ws[k*HID + j];
                d1 = fmaf(r1[k], w, d1);
                d2 = fmaf(r2[k], w, d2);
            }
            a1 += fast_tanh(d1);
            a2 += fast_tanh(d2);
        }
    }
    red1[tid] = a1; red2[tid] = a2;
    __syncthreads();
    if (slot == 0) {
        float s1 = 0.f, s2 = 0.f;
        #pragma unroll
        for (int ss = 0; ss < 8; ss++) { s1 += red1[ss*32 + j]; s2 += red2[ss*32 + j]; }
        atomicAdd(&g_tacc[par*64 + j], s1);
        atomicAdd(&g_tacc[par*64 + 32 + j], s2);
    }
}

// ---------------- final: inline attn + semantic combine + linear ---------------------
__global__ void final_kernel(const float* __restrict__ q2, const float* __restrict__ W,
                             const float* __restrict__ b, float* __restrict__ out) {
    __shared__ float sAttn[2];
    int tid = threadIdx.x;
    if (tid < 32) {                           // layer 2 parity = 0
        float qv = q2[tid];
        float p0 = g_tacc[tid] * qv;
        float p1 = g_tacc[32 + tid] * qv;
        #pragma unroll
        for (int o = 16; o >= 1; o >>= 1) {
            p0 += __shfl_xor_sync(0xffffffffu, p0, o);
            p1 += __shfl_xor_sync(0xffffffffu, p1, o);
        }
        if (tid == 0) {
            float s0 = p0 * (1.f / NADDR), s1 = p1 * (1.f / NADDR);
            float m = fmaxf(s0, s1);
            float e0 = __expf(s0 - m), e1 = __expf(s1 - m);
            sAttn[0] = e0 / (e0 + e1);
            sAttn[1] = e1 / (e0 + e1);
        }
    }
    __syncthreads();
    int n = blockIdx.x * blockDim.x + tid;
    if (n >= NADDR) return;
    float at0 = sAttn[0], at1 = sAttn[1];
    float a0 = b[0], a1 = b[1];
    const float* r1 = g_accA1 + (long)n*HID;
    const float* r2 = g_accA2 + (long)n*HID;
    #pragma unroll
    for (int k = 0; k < HID; k++) {
        float v = fmaxf(at0*r1[k] + at1*r2[k], 0.f);
        a0 = fmaf(v, W[k*2],     a0);
        a1 = fmaf(v, W[k*2 + 1], a1);
    }
    out[n*2] = a0;
    out[n*2 + 1] = a1;
}

// ---------------- host orchestration -------------------------------------------------
extern "C" void kernel_launch(void* const* d_in, const int* in_sizes, int n_in,
                              void* d_out, int out_size) {
    const float* x_addr  = (const float*)d_in[0];
    const float* x_tx    = (const float*)d_in[1];
    const int*   eat_s   = (const int*)d_in[2];
    const int*   eat_d   = (const int*)d_in[3];
    const int*   eta_s   = (const int*)d_in[4];
    const int*   eta_d   = (const int*)d_in[5];
    const int*   eaa_s   = (const int*)d_in[6];
    const int*   eaa_d   = (const int*)d_in[7];
    const float* pW1     = (const float*)d_in[8];
    const float* pb1     = (const float*)d_in[9];
    const float* pW23    = (const float*)d_in[10];
    const float* pb23    = (const float*)d_in[11];
    const float* att_src = (const float*)d_in[12];
    const float* att_dst = (const float*)d_in[13];
    const float* kW      = (const float*)d_in[14];
    const float* kb      = (const float*)d_in[15];
    const float* q       = (const float*)d_in[16];
    const float* linW    = (const float*)d_in[17];
    const float* linb    = (const float*)d_in[18];

    // CSR build (4 launches; counters re-zero themselves each invocation)
    csr_count_kernel<<<(EAT + 255)/256, 256>>>(eat_d, eta_d, eaa_d);
    csr_scan1_kernel<<<SB0 + SB1 + SB2, 256>>>();
    csr_scan3_kernel<<<(NTX + 255)/256, 256>>>();
    csr_scatter_kernel<<<(EAT + 255)/256, 256>>>(eat_s, eat_d, eta_s, eta_d, eaa_s, eaa_d);

    for (int l = 0; l < 3; l++) {
        const float *Wa, *ba, *Wt, *bt;
        int IN;
        if (l == 0) {
            Wa = pW1;               ba = pb1;
            Wt = pW1 + INDIM*HID;   bt = pb1 + HID;
            IN = INDIM;
        } else {
            Wa = pW23 + ((l-1)*2 + 0)*HID*HID;  ba = pb23 + ((l-1)*2 + 0)*HID;
            Wt = pW23 + ((l-1)*2 + 1)*HID*HID;  bt = pb23 + ((l-1)*2 + 1)*HID;
            IN = HID;
        }
        const float* As = att_src + (l*3) * HEADS * 8;
        const float* Ad = att_dst + (l*3) * HEADS * 8;
        const float* qp = (l == 0) ? q : q + (l-1)*HID;

        lin_alpha_kernel<<<NB_A + NB_T, 256>>>(l, x_addr, x_tx, Wa, ba, Wt, bt,
                                               As, Ad, qp, IN);
        agg_kernel<<<NB_T + NB_A + NB_A, 256>>>();
        sem_kernel<<<(NADDR + 255)/256, 256>>>(kW + l*HID*HID, kb + l*HID, l & 1);
    }
    final_kernel<<<(NADDR + 255)/256, 256>>>(q + 2*HID, linW, linb, (float*)d_out);
}